// round 11
// baseline (speedup 1.0000x reference)
#include <cuda_runtime.h>

#define HID   32
#define EMB   32
#define BD    32
#define VOCABN 50257
#define S_SRC 64
#define NSTEP 63
#define GSZ   (4*HID)   // 128 gates per layer

// ---------------- device scratch (no allocs allowed) ----------------
__device__ float g_h0[BD*HID];
__device__ float g_c0[BD*HID];
__device__ float g_h1[BD*HID];
__device__ float g_c1[BD*HID];
__device__ __align__(16) float g_h1T[HID*BD];   // [k][b], b contiguous
__device__ unsigned long long g_amax[BD];

// ---------------- helpers ----------------
__device__ __forceinline__ float sigf(float x){ return 1.f/(1.f+expf(-x)); }

__device__ __forceinline__ unsigned long long pk2(float lo, float hi){
    unsigned long long r;
    asm("mov.b64 %0, {%1, %2};" : "=l"(r) : "f"(lo), "f"(hi));
    return r;
}
// packed f32x2 fma: bit-identical per lane to scalar FFMA, 2x throughput
__device__ __forceinline__ unsigned long long ffma2(unsigned long long a,
                                                    unsigned long long b,
                                                    unsigned long long c){
    unsigned long long d;
    asm("fma.rn.f32x2 %0, %1, %2, %3;" : "=l"(d) : "l"(a), "l"(b), "l"(c));
    return d;
}
// order-preserving float -> uint mapping
__device__ __forceinline__ unsigned ordf(float f){
    unsigned u = __float_as_uint(f);
    return (u & 0x80000000u) ? ~u : (u | 0x80000000u);
}

// ================= encoder: 32 blocks (one per batch), 256 threads =================
// threads 0..127 own layer0 gate rows (weights in registers),
// threads 128..255 own layer1 gate rows.
__global__ void __launch_bounds__(256) enc_kernel(
    const int* __restrict__ x_src,
    const float* __restrict__ emb,
    const float* __restrict__ Wih0, const float* __restrict__ Whh0,
    const float* __restrict__ bih0, const float* __restrict__ bhh0,
    const float* __restrict__ Wih1, const float* __restrict__ Whh1,
    const float* __restrict__ bih1, const float* __restrict__ bhh1)
{
    const int b = blockIdx.x, tid = threadIdx.x;
    __shared__ float xs[EMB], h0s[HID], c0s[HID], h1s[HID], c1s[HID];
    __shared__ float gs[2*GSZ];

    float wi[HID], wh[HID], bias;
    if (tid < GSZ){
        #pragma unroll
        for (int k=0;k<HID;k++){ wi[k]=Wih0[tid*EMB+k]; wh[k]=Whh0[tid*HID+k]; }
        bias = bih0[tid] + bhh0[tid];
    } else {
        const int j = tid - GSZ;
        #pragma unroll
        for (int k=0;k<HID;k++){ wi[k]=Wih1[j*HID+k]; wh[k]=Whh1[j*HID+k]; }
        bias = bih1[j] + bhh1[j];
    }
    if (tid < HID){ h0s[tid]=0.f; c0s[tid]=0.f; h1s[tid]=0.f; c1s[tid]=0.f; }
    __syncthreads();

    for (int s=0;s<S_SRC;s++){
        if (tid < EMB) xs[tid] = emb[(size_t)x_src[s*BD+b]*EMB + tid];
        __syncthreads();
        if (tid < GSZ){
            float a0=bias, a1=0.f, a2=0.f, a3=0.f;
            #pragma unroll
            for (int k=0;k<HID;k+=4){
                a0=fmaf(xs[k],wi[k],a0);     a1=fmaf(xs[k+1],wi[k+1],a1);
                a2=fmaf(xs[k+2],wi[k+2],a2); a3=fmaf(xs[k+3],wi[k+3],a3);
            }
            #pragma unroll
            for (int k=0;k<HID;k+=4){
                a0=fmaf(h0s[k],wh[k],a0);     a1=fmaf(h0s[k+1],wh[k+1],a1);
                a2=fmaf(h0s[k+2],wh[k+2],a2); a3=fmaf(h0s[k+3],wh[k+3],a3);
            }
            gs[tid] = (a0+a1)+(a2+a3);
        }
        __syncthreads();
        if (tid < HID){
            float ig=sigf(gs[tid]),        fg=sigf(gs[HID+tid]);
            float gg=tanhf(gs[2*HID+tid]), og=sigf(gs[3*HID+tid]);
            float c2 = fg*c0s[tid] + ig*gg;
            c0s[tid]=c2; h0s[tid]=og*tanhf(c2);
        }
        __syncthreads();
        if (tid >= GSZ){
            float a0=bias, a1=0.f, a2=0.f, a3=0.f;
            #pragma unroll
            for (int k=0;k<HID;k+=4){
                a0=fmaf(h0s[k],wi[k],a0);     a1=fmaf(h0s[k+1],wi[k+1],a1);
                a2=fmaf(h0s[k+2],wi[k+2],a2); a3=fmaf(h0s[k+3],wi[k+3],a3);
            }
            #pragma unroll
            for (int k=0;k<HID;k+=4){
                a0=fmaf(h1s[k],wh[k],a0);     a1=fmaf(h1s[k+1],wh[k+1],a1);
                a2=fmaf(h1s[k+2],wh[k+2],a2); a3=fmaf(h1s[k+3],wh[k+3],a3);
            }
            gs[GSZ + (tid-GSZ)] = (a0+a1)+(a2+a3);
        }
        __syncthreads();
        if (tid < HID){
            float ig=sigf(gs[GSZ+tid]),        fg=sigf(gs[GSZ+HID+tid]);
            float gg=tanhf(gs[GSZ+2*HID+tid]), og=sigf(gs[GSZ+3*HID+tid]);
            float c2 = fg*c1s[tid] + ig*gg;
            c1s[tid]=c2; h1s[tid]=og*tanhf(c2);
        }
        __syncthreads();
    }
    if (tid < HID){
        g_h0[b*HID+tid]=h0s[tid]; g_c0[b*HID+tid]=c0s[tid];
        g_h1[b*HID+tid]=h1s[tid]; g_c1[b*HID+tid]=c1s[tid];
    }
    if (tid == 0) g_amax[b] = 0ull;   // re-armed every replay (determinism)
}

// ================= decoder cell: 32 blocks (one per batch), 256 threads =================
__global__ void __launch_bounds__(256) cell_kernel(
    int step, const int* __restrict__ x_tgt,
    const float* __restrict__ emb,
    const float* __restrict__ Wih0, const float* __restrict__ Whh0,
    const float* __restrict__ bih0, const float* __restrict__ bhh0,
    const float* __restrict__ Wih1, const float* __restrict__ Whh1,
    const float* __restrict__ bih1, const float* __restrict__ bhh1)
{
    const int b = blockIdx.x, tid = threadIdx.x;
    __shared__ float xs[EMB], h0s[HID], c0s[HID], h1s[HID], c1s[HID], gs[2*GSZ];
    __shared__ int toks;

    if (tid == 0){
        int tok;
        if (step == 0) tok = x_tgt[b];                 // x_tgt[0][b]
        else {
            unsigned long long k = g_amax[b];
            tok = (int)(0xFFFFFFFFu - (unsigned)(k & 0xFFFFFFFFull));
            g_amax[b] = 0ull;                          // re-arm for this step's logits
        }
        toks = tok;
    }
    if (tid < HID){
        h0s[tid]=g_h0[b*HID+tid]; c0s[tid]=g_c0[b*HID+tid];
        h1s[tid]=g_h1[b*HID+tid]; c1s[tid]=g_c1[b*HID+tid];
    }
    __syncthreads();
    if (tid < EMB) xs[tid] = emb[(size_t)toks*EMB + tid];
    __syncthreads();

    if (tid < GSZ){
        float a0 = bih0[tid]+bhh0[tid], a1=0.f, a2=0.f, a3=0.f;
        const float4* wi = (const float4*)(Wih0 + tid*EMB);
        const float4* wh = (const float4*)(Whh0 + tid*HID);
        #pragma unroll
        for (int q=0;q<8;q++){
            float4 w = wi[q];
            a0=fmaf(xs[4*q],w.x,a0);   a1=fmaf(xs[4*q+1],w.y,a1);
            a2=fmaf(xs[4*q+2],w.z,a2); a3=fmaf(xs[4*q+3],w.w,a3);
        }
        #pragma unroll
        for (int q=0;q<8;q++){
            float4 w = wh[q];
            a0=fmaf(h0s[4*q],w.x,a0);   a1=fmaf(h0s[4*q+1],w.y,a1);
            a2=fmaf(h0s[4*q+2],w.z,a2); a3=fmaf(h0s[4*q+3],w.w,a3);
        }
        gs[tid] = (a0+a1)+(a2+a3);
    }
    __syncthreads();
    if (tid < HID){
        float ig=sigf(gs[tid]),        fg=sigf(gs[HID+tid]);
        float gg=tanhf(gs[2*HID+tid]), og=sigf(gs[3*HID+tid]);
        float c2 = fg*c0s[tid] + ig*gg;
        float h2 = og*tanhf(c2);
        c0s[tid]=c2; h0s[tid]=h2;
        g_h0[b*HID+tid]=h2; g_c0[b*HID+tid]=c2;
    }
    __syncthreads();
    if (tid >= GSZ){
        const int j = tid - GSZ;
        float a0 = bih1[j]+bhh1[j], a1=0.f, a2=0.f, a3=0.f;
        const float4* wi = (const float4*)(Wih1 + j*HID);
        const float4* wh = (const float4*)(Whh1 + j*HID);
        #pragma unroll
        for (int q=0;q<8;q++){
            float4 w = wi[q];
            a0=fmaf(h0s[4*q],w.x,a0);   a1=fmaf(h0s[4*q+1],w.y,a1);
            a2=fmaf(h0s[4*q+2],w.z,a2); a3=fmaf(h0s[4*q+3],w.w,a3);
        }
        #pragma unroll
        for (int q=0;q<8;q++){
            float4 w = wh[q];
            a0=fmaf(h1s[4*q],w.x,a0);   a1=fmaf(h1s[4*q+1],w.y,a1);
            a2=fmaf(h1s[4*q+2],w.z,a2); a3=fmaf(h1s[4*q+3],w.w,a3);
        }
        gs[GSZ+j] = (a0+a1)+(a2+a3);
    }
    __syncthreads();
    if (tid < HID){
        float ig=sigf(gs[GSZ+tid]),        fg=sigf(gs[GSZ+HID+tid]);
        float gg=tanhf(gs[GSZ+2*HID+tid]), og=sigf(gs[GSZ+3*HID+tid]);
        float c2 = fg*c1s[tid] + ig*gg;
        float h2 = og*tanhf(c2);
        g_c1[b*HID+tid]=c2; g_h1[b*HID+tid]=h2;
        g_h1T[tid*BD + b] = h2;        // transposed, batch-contiguous, for logits kernel
    }
}

// ================= logits + argmax: 197 blocks x 256 threads, one vocab row per thread =================
__global__ void __launch_bounds__(256) logits_kernel(
    int step, const float* __restrict__ fcW, const float* __restrict__ fcb,
    float* __restrict__ out)
{
    __shared__ __align__(16) unsigned long long hp[HID*16];   // hp[k*16+p] = (h1[2p][k], h1[2p+1][k])
    __shared__ __align__(16) unsigned long long red[16*256];  // 32KB argmax scratch
    const int tid = threadIdx.x;

    for (int i=tid; i<HID*16; i+=256)
        hp[i] = ((const unsigned long long*)g_h1T)[i];
    __syncthreads();

    const int v  = blockIdx.x*256 + tid;
    const int vc = (v < VOCABN) ? v : (VOCABN-1);
    const float bias = fcb[vc];

    float w[HID];
    const float4* w4 = (const float4*)(fcW + (size_t)vc*HID);
    #pragma unroll
    for (int q=0;q<8;q++){
        float4 t = w4[q];
        w[4*q]=t.x; w[4*q+1]=t.y; w[4*q+2]=t.z; w[4*q+3]=t.w;
    }

    unsigned long long acc[16];
    {
        unsigned long long bb = pk2(bias, bias);
        #pragma unroll
        for (int p=0;p<16;p++) acc[p]=bb;
    }
    #pragma unroll
    for (int k=0;k<HID;k++){
        unsigned long long ww = pk2(w[k], w[k]);
        const ulonglong2* hr = (const ulonglong2*)(hp + k*16);
        #pragma unroll
        for (int q=0;q<8;q++){
            ulonglong2 h2 = hr[q];
            acc[2*q]   = ffma2(h2.x, ww, acc[2*q]);
            acc[2*q+1] = ffma2(h2.y, ww, acc[2*q+1]);
        }
    }

    if (v < VOCABN){
        float* o = out + ((size_t)step*BD)*VOCABN + v;
        #pragma unroll
        for (int p=0;p<16;p++){
            unsigned long long a = acc[p];
            o[(size_t)(2*p)*VOCABN]   = __uint_as_float((unsigned)(a & 0xFFFFFFFFull));
            o[(size_t)(2*p+1)*VOCABN] = __uint_as_float((unsigned)(a >> 32));
        }
    }

    // per-batch argmax: key = ordered(val)<<32 | (~v)  -> max key == first max value
    #pragma unroll
    for (int half=0; half<2; half++){
        #pragma unroll
        for (int r=0;r<16;r++){
            const int bb = half*16 + r;
            unsigned long long a = acc[bb>>1];
            unsigned u = (bb&1) ? (unsigned)(a>>32) : (unsigned)(a & 0xFFFFFFFFull);
            unsigned long long key = (v < VOCABN)
                ? ( ((unsigned long long)ordf(__uint_as_float(u)) << 32)
                    | (unsigned long long)(0xFFFFFFFFu - (unsigned)v) )
                : 0ull;
            red[r*256 + tid] = key;
        }
        __syncthreads();
        {
            const int row = tid>>4, col = tid&15;
            unsigned long long m = red[row*256+col];
            #pragma unroll
            for (int i=16;i<256;i+=16){
                unsigned long long x = red[row*256+col+i];
                if (x > m) m = x;
            }
            red[row*256+col] = m;
        }
        __syncthreads();
        if ((tid & 15) == 0){
            const int row = tid>>4;
            unsigned long long m = red[row*256];
            #pragma unroll
            for (int i=1;i<16;i++){
                unsigned long long x = red[row*256+i];
                if (x > m) m = x;
            }
            atomicMax(&g_amax[half*16 + row], m);
        }
        __syncthreads();
    }
}

// ================= launch =================
extern "C" void kernel_launch(void* const* d_in, const int* in_sizes, int n_in,
                              void* d_out, int out_size)
{
    const int*   x_src  = (const int*)  d_in[0];
    const int*   x_tgt  = (const int*)  d_in[1];
    const float* enc_emb= (const float*)d_in[2];
    const float* eWih0  = (const float*)d_in[3];
    const float* eWhh0  = (const float*)d_in[4];
    const float* ebih0  = (const float*)d_in[5];
    const float* ebhh0  = (const float*)d_in[6];
    const float* eWih1  = (const float*)d_in[7];
    const float* eWhh1  = (const float*)d_in[8];
    const float* ebih1  = (const float*)d_in[9];
    const float* ebhh1  = (const float*)d_in[10];
    const float* dec_emb= (const float*)d_in[11];
    const float* dWih0  = (const float*)d_in[12];
    const float* dWhh0  = (const float*)d_in[13];
    const float* dbih0  = (const float*)d_in[14];
    const float* dbhh0  = (const float*)d_in[15];
    const float* dWih1  = (const float*)d_in[16];
    const float* dWhh1  = (const float*)d_in[17];
    const float* dbih1  = (const float*)d_in[18];
    const float* dbhh1  = (const float*)d_in[19];
    const float* fcW    = (const float*)d_in[20];
    const float* fcb    = (const float*)d_in[21];
    float* out = (float*)d_out;

    enc_kernel<<<BD,256>>>(x_src, enc_emb,
                           eWih0,eWhh0,ebih0,ebhh0,eWih1,eWhh1,ebih1,ebhh1);

    const int lblocks = (VOCABN + 255) / 256;   // 197
    for (int t=0; t<NSTEP; t++){
        cell_kernel<<<BD,256>>>(t, x_tgt, dec_emb,
                                dWih0,dWhh0,dbih0,dbhh0,dWih1,dWhh1,dbih1,dbhh1);
        logits_kernel<<<lblocks,256>>>(t, fcW, fcb, out);
    }
}

// round 12
// speedup vs baseline: 1.2039x; 1.2039x over previous
#include <cuda_runtime.h>

#define HID    32
#define EMB    32
#define BD     32
#define VOCABN 50257
#define S_SRC  64
#define NSTEP  63
#define GSZ    (4*HID)     // 128 gate rows per layer
#define NB     296         // 2 blocks per SM on 148 SMs (<=304 on 152-SM GB300)
#define RPB    170         // vocab rows per block: 296*170 = 50320 >= 50257

// ---------------- device scratch (no allocs allowed) ----------------
__device__ __align__(16) float g_h1T[HID*BD];          // [k][b]
__device__ unsigned long long g_part[NB*BD];           // per-block argmax winners [bid][b]
__device__ unsigned g_arriveB, g_relB;                 // full grid barrier
__device__ unsigned g_cellArr, g_flagA;                // 32-producer release flag

// ---------------- helpers ----------------
__device__ __forceinline__ float sigf(float x){ return 1.f/(1.f+expf(-x)); }

__device__ __forceinline__ unsigned long long pk2(float lo, float hi){
    unsigned long long r;
    asm("mov.b64 %0, {%1, %2};" : "=l"(r) : "f"(lo), "f"(hi));
    return r;
}
__device__ __forceinline__ unsigned long long ffma2(unsigned long long a,
                                                    unsigned long long b,
                                                    unsigned long long c){
    unsigned long long d;
    asm("fma.rn.f32x2 %0, %1, %2, %3;" : "=l"(d) : "l"(a), "l"(b), "l"(c));
    return d;
}
// order-preserving float-bits -> uint mapping
__device__ __forceinline__ unsigned ordb(unsigned u){
    return (u & 0x80000000u) ? ~u : (u | 0x80000000u);
}

// ================= the one persistent kernel =================
__global__ void __launch_bounds__(256, 2) mega_kernel(
    const int* __restrict__ x_src, const int* __restrict__ x_tgt,
    const float* __restrict__ enc_emb,
    const float* __restrict__ eWih0, const float* __restrict__ eWhh0,
    const float* __restrict__ ebih0, const float* __restrict__ ebhh0,
    const float* __restrict__ eWih1, const float* __restrict__ eWhh1,
    const float* __restrict__ ebih1, const float* __restrict__ ebhh1,
    const float* __restrict__ dec_emb,
    const float* __restrict__ dWih0, const float* __restrict__ dWhh0,
    const float* __restrict__ dbih0, const float* __restrict__ dbhh0,
    const float* __restrict__ dWih1, const float* __restrict__ dWhh1,
    const float* __restrict__ dbih1, const float* __restrict__ dbhh1,
    const float* __restrict__ fcW,   const float* __restrict__ fcb,
    float* __restrict__ out)
{
    const int bid = blockIdx.x, tid = threadIdx.x;
    __shared__ float xs[EMB], h0s[HID], c0s[HID], h1s[HID], c1s[HID];
    __shared__ float gs[2*GSZ];
    __shared__ __align__(16) unsigned long long hp[HID*16];   // (h[k][2p], h[k][2p+1])
    __shared__ unsigned long long cand[256];                  // warp argmax candidates
    __shared__ int toks;

    // base values of the monotonic phase counters (replay-safe: no one writes
    // either counter until EVERY block has arrived at the initial barrier below,
    // and a block only arrives after reading both bases).
    const unsigned baseA = *(volatile unsigned*)&g_flagA;
    const unsigned baseB = *(volatile unsigned*)&g_relB;

    // ---- initial full grid barrier ----
    __syncthreads();
    if (tid == 0){
        __threadfence();
        if (atomicAdd(&g_arriveB, 1u) == NB-1u){
            atomicExch(&g_arriveB, 0u);
            __threadfence();
            atomicExch(&g_relB, baseB + 1u);
        } else {
            while ((int)(*(volatile unsigned*)&g_relB - (baseB + 1u)) < 0) {}
        }
    }
    __syncthreads();

    // ================= encoder (blocks 0..31, one batch each) =================
    if (bid < BD){
        float wi[HID], wh[HID], bias2;
        if (tid < GSZ){
            #pragma unroll
            for (int k=0;k<HID;k++){ wi[k]=eWih0[tid*EMB+k]; wh[k]=eWhh0[tid*HID+k]; }
            bias2 = ebih0[tid] + ebhh0[tid];
        } else {
            const int j = tid - GSZ;
            #pragma unroll
            for (int k=0;k<HID;k++){ wi[k]=eWih1[j*HID+k]; wh[k]=eWhh1[j*HID+k]; }
            bias2 = ebih1[j] + ebhh1[j];
        }
        if (tid < HID){ h0s[tid]=0.f; c0s[tid]=0.f; h1s[tid]=0.f; c1s[tid]=0.f; }
        __syncthreads();

        for (int s=0;s<S_SRC;s++){
            if (tid < EMB) xs[tid] = enc_emb[(size_t)x_src[s*BD+bid]*EMB + tid];
            __syncthreads();
            if (tid < GSZ){
                float a0=bias2, a1=0.f, a2=0.f, a3=0.f;
                #pragma unroll
                for (int k=0;k<HID;k+=4){
                    a0=fmaf(xs[k],wi[k],a0);     a1=fmaf(xs[k+1],wi[k+1],a1);
                    a2=fmaf(xs[k+2],wi[k+2],a2); a3=fmaf(xs[k+3],wi[k+3],a3);
                }
                #pragma unroll
                for (int k=0;k<HID;k+=4){
                    a0=fmaf(h0s[k],wh[k],a0);     a1=fmaf(h0s[k+1],wh[k+1],a1);
                    a2=fmaf(h0s[k+2],wh[k+2],a2); a3=fmaf(h0s[k+3],wh[k+3],a3);
                }
                gs[tid] = (a0+a1)+(a2+a3);
            }
            __syncthreads();
            if (tid < HID){
                float ig=sigf(gs[tid]),        fg=sigf(gs[HID+tid]);
                float gg=tanhf(gs[2*HID+tid]), og=sigf(gs[3*HID+tid]);
                float c2 = fg*c0s[tid] + ig*gg;
                c0s[tid]=c2; h0s[tid]=og*tanhf(c2);
            }
            __syncthreads();
            if (tid >= GSZ){
                float a0=bias2, a1=0.f, a2=0.f, a3=0.f;
                #pragma unroll
                for (int k=0;k<HID;k+=4){
                    a0=fmaf(h0s[k],wi[k],a0);     a1=fmaf(h0s[k+1],wi[k+1],a1);
                    a2=fmaf(h0s[k+2],wi[k+2],a2); a3=fmaf(h0s[k+3],wi[k+3],a3);
                }
                #pragma unroll
                for (int k=0;k<HID;k+=4){
                    a0=fmaf(h1s[k],wh[k],a0);     a1=fmaf(h1s[k+1],wh[k+1],a1);
                    a2=fmaf(h1s[k+2],wh[k+2],a2); a3=fmaf(h1s[k+3],wh[k+3],a3);
                }
                gs[GSZ + (tid-GSZ)] = (a0+a1)+(a2+a3);
            }
            __syncthreads();
            if (tid < HID){
                float ig=sigf(gs[GSZ+tid]),        fg=sigf(gs[GSZ+HID+tid]);
                float gg=tanhf(gs[GSZ+2*HID+tid]), og=sigf(gs[GSZ+3*HID+tid]);
                float c2 = fg*c1s[tid] + ig*gg;
                c1s[tid]=c2; h1s[tid]=og*tanhf(c2);
            }
            __syncthreads();
        }
        // decoder initial state stays resident in this block's smem
    }

    // ================= persistent fc weights (one vocab row / thread) =================
    const int v  = bid*RPB + tid;
    const int vc = (tid < RPB && v < VOCABN) ? v : (VOCABN-1);
    float w[HID];
    {
        const float4* w4 = (const float4*)(fcW + (size_t)vc*HID);
        #pragma unroll
        for (int q=0;q<8;q++){
            float4 t4 = w4[q];
            w[4*q]=t4.x; w[4*q+1]=t4.y; w[4*q+2]=t4.z; w[4*q+3]=t4.w;
        }
    }
    const float bias = fcb[vc];

    // ================= decoder loop =================
    for (int t=0;t<NSTEP;t++){
        // ---------- cell (blocks 0..31) ----------
        if (bid < BD){
            if (t == 0){
                if (tid == 0) toks = x_tgt[bid];
            } else {
                // reduce the 296 per-block winners for batch `bid`
                unsigned long long m = 0ull;
                {
                    unsigned long long k0 = __ldcg(&g_part[tid*BD + bid]);
                    if (k0 > m) m = k0;
                    int idx = tid + 256;
                    if (idx < NB){
                        unsigned long long k1 = __ldcg(&g_part[idx*BD + bid]);
                        if (k1 > m) m = k1;
                    }
                }
                #pragma unroll
                for (int off=16; off; off>>=1){
                    unsigned long long o2 = __shfl_down_sync(0xFFFFFFFFu, m, off);
                    if (o2 > m) m = o2;
                }
                if ((tid & 31) == 0) cand[tid>>5] = m;
                __syncthreads();
                if (tid == 0){
                    unsigned long long mm = cand[0];
                    #pragma unroll
                    for (int i=1;i<8;i++) if (cand[i] > mm) mm = cand[i];
                    toks = (int)(0xFFFFFFFFu - (unsigned)(mm & 0xFFFFFFFFull));
                }
            }
            __syncthreads();
            if (tid < EMB) xs[tid] = dec_emb[(size_t)toks*EMB + tid];
            __syncthreads();

            if (tid < GSZ){
                float a0 = dbih0[tid]+dbhh0[tid], a1=0.f, a2=0.f, a3=0.f;
                const float4* wi4 = (const float4*)(dWih0 + tid*EMB);
                const float4* wh4 = (const float4*)(dWhh0 + tid*HID);
                #pragma unroll
                for (int q=0;q<8;q++){
                    float4 ww = wi4[q];
                    a0=fmaf(xs[4*q],ww.x,a0);   a1=fmaf(xs[4*q+1],ww.y,a1);
                    a2=fmaf(xs[4*q+2],ww.z,a2); a3=fmaf(xs[4*q+3],ww.w,a3);
                }
                #pragma unroll
                for (int q=0;q<8;q++){
                    float4 ww = wh4[q];
                    a0=fmaf(h0s[4*q],ww.x,a0);   a1=fmaf(h0s[4*q+1],ww.y,a1);
                    a2=fmaf(h0s[4*q+2],ww.z,a2); a3=fmaf(h0s[4*q+3],ww.w,a3);
                }
                gs[tid] = (a0+a1)+(a2+a3);
            }
            __syncthreads();
            if (tid < HID){
                float ig=sigf(gs[tid]),        fg=sigf(gs[HID+tid]);
                float gg=tanhf(gs[2*HID+tid]), og=sigf(gs[3*HID+tid]);
                float c2 = fg*c0s[tid] + ig*gg;
                c0s[tid]=c2; h0s[tid]=og*tanhf(c2);
            }
            __syncthreads();
            if (tid >= GSZ){
                const int j = tid - GSZ;
                float a0 = dbih1[j]+dbhh1[j], a1=0.f, a2=0.f, a3=0.f;
                const float4* wi4 = (const float4*)(dWih1 + j*HID);
                const float4* wh4 = (const float4*)(dWhh1 + j*HID);
                #pragma unroll
                for (int q=0;q<8;q++){
                    float4 ww = wi4[q];
                    a0=fmaf(h0s[4*q],ww.x,a0);   a1=fmaf(h0s[4*q+1],ww.y,a1);
                    a2=fmaf(h0s[4*q+2],ww.z,a2); a3=fmaf(h0s[4*q+3],ww.w,a3);
                }
                #pragma unroll
                for (int q=0;q<8;q++){
                    float4 ww = wh4[q];
                    a0=fmaf(h1s[4*q],ww.x,a0);   a1=fmaf(h1s[4*q+1],ww.y,a1);
                    a2=fmaf(h1s[4*q+2],ww.z,a2); a3=fmaf(h1s[4*q+3],ww.w,a3);
                }
                gs[GSZ+j] = (a0+a1)+(a2+a3);
            }
            __syncthreads();
            if (tid < HID){
                float ig=sigf(gs[GSZ+tid]),        fg=sigf(gs[GSZ+HID+tid]);
                float gg=tanhf(gs[GSZ+2*HID+tid]), og=sigf(gs[GSZ+3*HID+tid]);
                float c2 = fg*c1s[tid] + ig*gg;
                float h2 = og*tanhf(c2);
                c1s[tid]=c2; h1s[tid]=h2;
                g_h1T[tid*BD + bid] = h2;
            }
            __syncthreads();
            if (tid == 0){
                __threadfence();
                if (atomicAdd(&g_cellArr, 1u) == BD-1u){
                    atomicExch(&g_cellArr, 0u);
                    __threadfence();
                    atomicExch(&g_flagA, baseA + 1u + (unsigned)t);
                }
            }
        }

        // ---------- wait: h1T(t) ready ----------
        if (tid == 0){
            const unsigned tgt = baseA + 1u + (unsigned)t;
            while ((int)(*(volatile unsigned*)&g_flagA - tgt) < 0) {}
        }
        __syncthreads();

        // ---------- logits (all blocks) ----------
        for (int i=tid; i<HID*16; i+=256)
            hp[i] = __ldcg(((const unsigned long long*)g_h1T) + i);
        cand[tid] = 0ull;
        __syncthreads();

        unsigned long long acc[16];
        {
            unsigned long long bb = pk2(bias, bias);
            #pragma unroll
            for (int p=0;p<16;p++) acc[p]=bb;
        }
        #pragma unroll
        for (int k=0;k<HID;k++){
            unsigned long long ww = pk2(w[k], w[k]);
            const ulonglong2* hr = (const ulonglong2*)(hp + k*16);
            #pragma unroll
            for (int q=0;q<8;q++){
                ulonglong2 h2 = hr[q];
                acc[2*q]   = ffma2(h2.x, ww, acc[2*q]);
                acc[2*q+1] = ffma2(h2.y, ww, acc[2*q+1]);
            }
        }

        if (tid < RPB && v < VOCABN){
            float* o = out + ((size_t)t*BD)*VOCABN + v;
            #pragma unroll
            for (int p=0;p<16;p++){
                unsigned long long a = acc[p];
                o[(size_t)(2*p)*VOCABN]   = __uint_as_float((unsigned)(a & 0xFFFFFFFFull));
                o[(size_t)(2*p+1)*VOCABN] = __uint_as_float((unsigned)(a >> 32));
            }
        }

        // ---------- per-warp argmax (warps 0..5 cover RPB=170 rows) ----------
        if (tid < 192){
            const bool valid = (tid < RPB) && (v < VOCABN);
            const unsigned vk = 0xFFFFFFFFu - (unsigned)v;
            #pragma unroll
            for (int b=0;b<BD;b++){
                unsigned long long a = acc[b>>1];
                unsigned u = (b&1) ? (unsigned)(a>>32) : (unsigned)(a & 0xFFFFFFFFull);
                unsigned o_ = valid ? ordb(u) : 0u;
                unsigned mx = __reduce_max_sync(0xFFFFFFFFu, o_);
                unsigned ball = __ballot_sync(0xFFFFFFFFu, (o_ == mx) && valid);
                if (ball){
                    int leader = __ffs(ball) - 1;
                    if ((tid & 31) == leader)
                        cand[(tid>>5)*BD + b] = ((unsigned long long)mx << 32) | (unsigned long long)vk;
                }
            }
        }
        __syncthreads();
        if (tid < BD){
            unsigned long long m = cand[tid];
            #pragma unroll
            for (int wq=1;wq<6;wq++){
                unsigned long long k = cand[wq*BD + tid];
                if (k > m) m = k;
            }
            g_part[bid*BD + tid] = m;
        }

        // ---------- full grid barrier: g_part(t) ready ----------
        if (t < NSTEP-1){
            __syncthreads();
            if (tid == 0){
                __threadfence();
                const unsigned tgt = baseB + 2u + (unsigned)t;
                if (atomicAdd(&g_arriveB, 1u) == NB-1u){
                    atomicExch(&g_arriveB, 0u);
                    __threadfence();
                    atomicExch(&g_relB, tgt);
                } else {
                    while ((int)(*(volatile unsigned*)&g_relB - tgt) < 0) {}
                }
            }
            __syncthreads();
        }
    }
}

// ================= launch =================
extern "C" void kernel_launch(void* const* d_in, const int* in_sizes, int n_in,
                              void* d_out, int out_size)
{
    const int*   x_src  = (const int*)  d_in[0];
    const int*   x_tgt  = (const int*)  d_in[1];
    const float* enc_emb= (const float*)d_in[2];
    const float* eWih0  = (const float*)d_in[3];
    const float* eWhh0  = (const float*)d_in[4];
    const float* ebih0  = (const float*)d_in[5];
    const float* ebhh0  = (const float*)d_in[6];
    const float* eWih1  = (const float*)d_in[7];
    const float* eWhh1  = (const float*)d_in[8];
    const float* ebih1  = (const float*)d_in[9];
    const float* ebhh1  = (const float*)d_in[10];
    const float* dec_emb= (const float*)d_in[11];
    const float* dWih0  = (const float*)d_in[12];
    const float* dWhh0  = (const float*)d_in[13];
    const float* dbih0  = (const float*)d_in[14];
    const float* dbhh0  = (const float*)d_in[15];
    const float* dWih1  = (const float*)d_in[16];
    const float* dWhh1  = (const float*)d_in[17];
    const float* dbih1  = (const float*)d_in[18];
    const float* dbhh1  = (const float*)d_in[19];
    const float* fcW    = (const float*)d_in[20];
    const float* fcb    = (const float*)d_in[21];
    float* out = (float*)d_out;

    mega_kernel<<<NB, 256>>>(x_src, x_tgt, enc_emb,
                             eWih0,eWhh0,ebih0,ebhh0,eWih1,eWhh1,ebih1,ebhh1,
                             dec_emb,
                             dWih0,dWhh0,dbih0,dbhh0,dWih1,dWhh1,dbih1,dbhh1,
                             fcW, fcb, out);
}